// round 12
// baseline (speedup 1.0000x reference)
#include <cuda_runtime.h>
#include <cuda_bf16.h>
#include <cstdint>

#define NSITES   50000
#define NPERM    12
#define NNEIGH   8
#define INF      512
#define OUTF     64
#define LN2F     0.6931471805599453f

#define TOTROWS  (NSITES * NPERM)                  // 600000
#define BM       128
#define NBLOCKS  ((TOTROWS + BM - 1) / BM)         // 4688
#define NTHREADS 256
#define NCHUNK   8
#define WS       72        // padded smem row stride in bf16 elems (144 B)

// ---------------- SMEM layout (bytes, dynamic) ----------------
#define SM_BIAS  0                          // 64 f32 = 256 B
#define SM_IDX   256                        // 128*8 int = 4096 B
#define SM_WHI   4352                       // 64*144 = 9216 B
#define SM_WLO   13568                      // 9216 B -> ends 22784
#define SM_A0    22784                      // two A buffers, each hi(18432)+lo(18432)
#define ABUF     36864
#define SM_TOTAL (SM_A0 + 2 * ABUF)         // 96512
#define SM_RED   SM_A0                      // epilogue reuse: 128*64 f32 = 32768 B

// ---------------- global split buffers ----------------
__device__ __nv_bfloat16 g_Whi[NCHUNK * 64 * 64];   // [c][n][kk], kk contiguous
__device__ __nv_bfloat16 g_Wlo[NCHUNK * 64 * 64];
__device__ __nv_bfloat16 g_Xhi[NSITES * 64];
__device__ __nv_bfloat16 g_Xlo[NSITES * 64];

// ---------------- pre-kernels ----------------
__global__ void split_W_kernel(const float* __restrict__ W) {
    int i = blockIdx.x * blockDim.x + threadIdx.x;
    if (i < OUTF * INF) {
        int n = i >> 9, k = i & 511, c = k >> 6, kk = k & 63;
        float v = W[i];
        __nv_bfloat16 h = __float2bfloat16(v);
        float r = v - __bfloat162float(h);
        int j = c * 4096 + n * 64 + kk;
        g_Whi[j] = h;
        g_Wlo[j] = __float2bfloat16(r);
    }
}
__global__ void split_X_kernel(const float* __restrict__ X) {
    int i = blockIdx.x * blockDim.x + threadIdx.x;
    if (i < NSITES * 64) {
        float v = X[i];
        __nv_bfloat16 h = __float2bfloat16(v);
        g_Xhi[i] = h;
        g_Xlo[i] = __float2bfloat16(v - __bfloat162float(h));
    }
}
__global__ void zero_out_kernel(float* __restrict__ out) {
    int i = blockIdx.x * blockDim.x + threadIdx.x;
    if (i < NSITES * OUTF) out[i] = 0.0f;
}

// ---------------- PTX helpers ----------------
__device__ __forceinline__ uint32_t smem_u32(const void* p) {
    uint32_t a;
    asm("{ .reg .u64 t; cvta.to.shared.u64 t, %1; cvt.u32.u64 %0, t; }" : "=r"(a) : "l"(p));
    return a;
}
__device__ __forceinline__ void mma_bf16(float* d, const uint32_t* a,
                                         uint32_t b0, uint32_t b1) {
    asm volatile(
        "mma.sync.aligned.m16n8k16.row.col.f32.bf16.bf16.f32 "
        "{%0,%1,%2,%3}, {%4,%5,%6,%7}, {%8,%9}, {%0,%1,%2,%3};\n"
        : "+f"(d[0]), "+f"(d[1]), "+f"(d[2]), "+f"(d[3])
        : "r"(a[0]), "r"(a[1]), "r"(a[2]), "r"(a[3]), "r"(b0), "r"(b1));
}
#define LDSM_X4(R, A) \
    asm volatile("ldmatrix.sync.aligned.m8n8.x4.shared.b16 {%0,%1,%2,%3}, [%4];" \
        : "=r"((R)[0]), "=r"((R)[1]), "=r"((R)[2]), "=r"((R)[3]) : "r"(A))

// ---------------- main kernel ----------------
__global__ __launch_bounds__(NTHREADS)
void lcnn_mma_kernel(const int* __restrict__ NS,
                     const float* __restrict__ bias,
                     float* __restrict__ out)
{
    extern __shared__ char smem[];
    const int tid = threadIdx.x;
    const int wid = tid >> 5;     // 0..7
    const int lid = tid & 31;
    const int g   = lid >> 2;     // 0..7
    const int tg  = lid & 3;      // 0..3
    const int blk = blockIdx.x;

    const int R0    = blk * BM;
    const int valid = min(BM, TOTROWS - R0);

    if (tid < OUTF) *(float*)(smem + SM_BIAS + tid * 4) = bias[tid];

    int* idx_sm = (int*)(smem + SM_IDX);
    for (int i = tid; i < BM * NNEIGH; i += NTHREADS)
        idx_sm[i] = (i < valid * NNEIGH) ? NS[(long)R0 * NNEIGH + i] : 0;
    __syncthreads();     // idx visible before any gather

    const uint4* Xhi4 = (const uint4*)g_Xhi;
    const uint4* Xlo4 = (const uint4*)g_Xlo;
    const uint4* GWh4 = (const uint4*)g_Whi;
    const uint4* GWl4 = (const uint4*)g_Wlo;

    // ldmatrix lane base offsets (bytes)
    // A tiles t=lid>>3: m_add=(t&1)*8, k_add=(t>>1)*8 ; rows wid*16..
    const uint32_t abase =
        (uint32_t)(wid * 16 + ((lid >> 3) & 1) * 8 + (lid & 7)) * 144 +
        (uint32_t)(((lid >> 4) & 1) * 8) * 2;
    // W tiles t=lid>>3: n_add=(t>>1)*8, k_add=(t&1)*8 ; pair np adds np*16 rows
    const uint32_t wbase =
        (uint32_t)(((lid >> 4) & 1) * 8 + (lid & 7)) * 144 +
        (uint32_t)(((lid >> 3) & 1) * 8) * 2;

    const uint32_t WH = smem_u32(smem + SM_WHI);
    const uint32_t WL = smem_u32(smem + SM_WLO);
    const uint32_t A0 = smem_u32(smem + SM_A0);

    float acc[8][4];
    #pragma unroll
    for (int nt = 0; nt < 8; nt++)
        #pragma unroll
        for (int e = 0; e < 4; e++)
            acc[nt][e] = 0.0f;

    // gather registers for the in-flight chunk
    uint4 arh[4], arl[4], wrh[2], wrl[2];

    // gather chunk c into regs
    auto gatherc = [&](int c) {
        #pragma unroll
        for (int it = 0; it < 4; it++) {
            int linear = tid + it * NTHREADS;   // < 1024
            int m = linear >> 3, u = linear & 7;
            int nb = idx_sm[m * NNEIGH + c];
            arh[it] = Xhi4[nb * 8 + u];
            arl[it] = Xlo4[nb * 8 + u];
        }
        #pragma unroll
        for (int it = 0; it < 2; it++) {
            int u = tid + it * NTHREADS;        // < 512
            wrh[it] = GWh4[c * 512 + u];
            wrl[it] = GWl4[c * 512 + u];
        }
    };
    auto sts_A = [&](int b) {
        uint4* Ah = (uint4*)(smem + SM_A0 + b * ABUF);
        uint4* Al = (uint4*)(smem + SM_A0 + b * ABUF + 18432);
        #pragma unroll
        for (int it = 0; it < 4; it++) {
            int linear = tid + it * NTHREADS;
            int m = linear >> 3, u = linear & 7;
            Ah[m * 9 + u] = arh[it];
            Al[m * 9 + u] = arl[it];
        }
    };
    auto sts_W = [&]() {
        uint4* Wh = (uint4*)(smem + SM_WHI);
        uint4* Wl = (uint4*)(smem + SM_WLO);
        #pragma unroll
        for (int it = 0; it < 2; it++) {
            int u = tid + it * NTHREADS;
            int n = u >> 3, uu = u & 7;
            Wh[n * 9 + uu] = wrh[it];
            Wl[n * 9 + uu] = wrl[it];
        }
    };

    // prologue: stage chunk 0
    gatherc(0);
    sts_A(0);
    sts_W();
    __syncthreads();

    for (int c = 0; c < NCHUNK; c++) {
        const int b = c & 1;
        if (c + 1 < NCHUNK) gatherc(c + 1);    // LDGs in flight over the MMA burst

        const uint32_t AHI = A0 + b * ABUF;
        const uint32_t ALO = AHI + 18432;
        #pragma unroll
        for (int ks = 0; ks < 4; ks++) {
            const uint32_t Kb = (uint32_t)(ks * 16) * 2;   // bytes
            uint32_t ah[4], al[4];
            LDSM_X4(ah, AHI + abase + Kb);
            LDSM_X4(al, ALO + abase + Kb);
            #pragma unroll
            for (int np = 0; np < 4; np++) {
                uint32_t bh[4], bl[4];
                LDSM_X4(bh, WH + wbase + (uint32_t)(np * 16) * 144 + Kb);
                LDSM_X4(bl, WL + wbase + (uint32_t)(np * 16) * 144 + Kb);
                mma_bf16(acc[np * 2 + 0], ah, bh[0], bh[1]);
                mma_bf16(acc[np * 2 + 1], ah, bh[2], bh[3]);
                mma_bf16(acc[np * 2 + 0], ah, bl[0], bl[1]);
                mma_bf16(acc[np * 2 + 1], ah, bl[2], bl[3]);
                mma_bf16(acc[np * 2 + 0], al, bh[0], bh[1]);
                mma_bf16(acc[np * 2 + 1], al, bh[2], bh[3]);
            }
        }

        if (c + 1 < NCHUNK) {
            sts_A(1 - b);        // other buffer: safe, last read was chunk c-1 (synced)
            __syncthreads();     // all warps done with MMA chunk c (W reads complete)
            sts_W();
            __syncthreads();     // W chunk c+1 visible
        }
    }

    // Epilogue: bias + shifted softplus -> smem red buffer [128][64] f32
    // (red aliases A buf 0; chunk 7 read buf 1, chunk 6 readers synced -> safe)
    float* red = (float*)(smem + SM_RED);
    const float* bsm = (const float*)(smem + SM_BIAS);
    const int row0 = wid * 16 + g;
    #pragma unroll
    for (int nt = 0; nt < 8; nt++) {
        const int col = nt * 8 + 2 * tg;
        const float b0 = bsm[col], b1 = bsm[col + 1];
        float x, s0, s1;
        x = acc[nt][0] + b0;
        s0 = fmaxf(x, 0.0f) + __logf(1.0f + __expf(-fabsf(x))) - LN2F;
        x = acc[nt][1] + b1;
        s1 = fmaxf(x, 0.0f) + __logf(1.0f + __expf(-fabsf(x))) - LN2F;
        *(float2*)&red[row0 * 64 + col] = make_float2(s0, s1);
        x = acc[nt][2] + b0;
        s0 = fmaxf(x, 0.0f) + __logf(1.0f + __expf(-fabsf(x))) - LN2F;
        x = acc[nt][3] + b1;
        s1 = fmaxf(x, 0.0f) + __logf(1.0f + __expf(-fabsf(x))) - LN2F;
        *(float2*)&red[(row0 + 8) * 64 + col] = make_float2(s0, s1);
    }
    __syncthreads();

    // Per-site perm sums. Sites can straddle tile boundaries -> <=2 atomic
    // contributions per output; float add of 2 terms is order-independent.
    {
        int s0 = R0 / NPERM;
        int s1 = (R0 + valid - 1) / NPERM;
        int nout = (s1 - s0 + 1) * OUTF;
        for (int i = tid; i < nout; i += NTHREADS) {
            int site = s0 + (i >> 6);
            int col  = i & 63;
            int rbeg = max(site * NPERM, R0);
            int rend = min(site * NPERM + NPERM, R0 + valid);
            float v = 0.0f;
            for (int r = rbeg; r < rend; r++)
                v += red[(r - R0) * 64 + col];
            atomicAdd(&out[(long)site * OUTF + col], v);
        }
    }
}

extern "C" void kernel_launch(void* const* d_in, const int* in_sizes, int n_in,
                              void* d_out, int out_size) {
    const float* X  = (const float*)d_in[0];   // X_sites (50000,64) f32
    const int*   NS = (const int*)  d_in[1];   // X_NSs   (50000,12,8) i32
    const float* W  = (const float*)d_in[2];   // W       (64,512) f32
    const float* b  = (const float*)d_in[3];   // b       (64,) f32
    float* out = (float*)d_out;                // (50000,64) f32

    cudaFuncSetAttribute(lcnn_mma_kernel,
                         cudaFuncAttributeMaxDynamicSharedMemorySize, SM_TOTAL);

    split_W_kernel<<<(OUTF * INF + 255) / 256, 256>>>(W);
    split_X_kernel<<<(NSITES * 64 + 255) / 256, 256>>>(X);
    zero_out_kernel<<<(NSITES * OUTF + 255) / 256, 256>>>(out);
    lcnn_mma_kernel<<<NBLOCKS, NTHREADS, SM_TOTAL>>>(NS, b, out);
}

// round 13
// speedup vs baseline: 1.5238x; 1.5238x over previous
#include <cuda_runtime.h>
#include <cuda_bf16.h>
#include <cstdint>

#define NSITES   50000
#define NPERM    12
#define NNEIGH   8
#define INF      512
#define OUTF     64
#define LN2F     0.6931471805599453f

#define TOTROWS  (NSITES * NPERM)                  // 600000
#define BM       128
#define NBLOCKS  ((TOTROWS + BM - 1) / BM)         // 4688
#define NTHREADS 256
#define NCHUNK   8

// ---------------- SMEM layout (bytes, dynamic) ----------------
#define SM_BIAS  0                      // 64 f32 = 256 B
#define SM_IDX   256                    // 128*8 int = 4096 B
#define SM_W     5120                   // 2 bufs x (hi 8192 + lo 8192)
#define WBUF     16384
#define SM_A     38912                  // 2 bufs x (hi 16384 + lo 16384)
#define ABUF     32768
#define SM_TOTAL 104448
#define SM_RED   SM_A                   // epilogue reuse: 128*64 f32 = 32768 B

// ---------------- global split buffers ----------------
__device__ __nv_bfloat16 g_Whi[NCHUNK * 64 * 64];   // [c][n][kk], kk contiguous
__device__ __nv_bfloat16 g_Wlo[NCHUNK * 64 * 64];
__device__ __nv_bfloat16 g_Xhi[NSITES * 64];
__device__ __nv_bfloat16 g_Xlo[NSITES * 64];

// ---------------- pre-kernels ----------------
__global__ void split_W_kernel(const float* __restrict__ W) {
    int i = blockIdx.x * blockDim.x + threadIdx.x;
    if (i < OUTF * INF) {
        int n = i >> 9, k = i & 511, c = k >> 6, kk = k & 63;
        float v = W[i];
        __nv_bfloat16 h = __float2bfloat16(v);
        float r = v - __bfloat162float(h);
        int j = c * 4096 + n * 64 + kk;
        g_Whi[j] = h;
        g_Wlo[j] = __float2bfloat16(r);
    }
}
__global__ void split_X_kernel(const float* __restrict__ X) {
    int i = blockIdx.x * blockDim.x + threadIdx.x;
    if (i < NSITES * 64) {
        float v = X[i];
        __nv_bfloat16 h = __float2bfloat16(v);
        g_Xhi[i] = h;
        g_Xlo[i] = __float2bfloat16(v - __bfloat162float(h));
    }
}
__global__ void zero_out_kernel(float* __restrict__ out) {
    int i = blockIdx.x * blockDim.x + threadIdx.x;
    if (i < NSITES * OUTF) out[i] = 0.0f;
}

// ---------------- PTX helpers ----------------
__device__ __forceinline__ uint32_t smem_u32(const void* p) {
    uint32_t a;
    asm("{ .reg .u64 t; cvta.to.shared.u64 t, %1; cvt.u32.u64 %0, t; }" : "=r"(a) : "l"(p));
    return a;
}
__device__ __forceinline__ void cp16(uint32_t dst, const void* src) {
    asm volatile("cp.async.cg.shared.global [%0], [%1], 16;" :: "r"(dst), "l"(src) : "memory");
}
#define CP_COMMIT() asm volatile("cp.async.commit_group;" ::: "memory")
#define CP_WAIT0()  asm volatile("cp.async.wait_group 0;" ::: "memory")
__device__ __forceinline__ void mma_bf16(float* d, const uint32_t* a,
                                         uint32_t b0, uint32_t b1) {
    asm volatile(
        "mma.sync.aligned.m16n8k16.row.col.f32.bf16.bf16.f32 "
        "{%0,%1,%2,%3}, {%4,%5,%6,%7}, {%8,%9}, {%0,%1,%2,%3};\n"
        : "+f"(d[0]), "+f"(d[1]), "+f"(d[2]), "+f"(d[3])
        : "r"(a[0]), "r"(a[1]), "r"(a[2]), "r"(a[3]), "r"(b0), "r"(b1));
}
#define LDSM_X4(R, A) \
    asm volatile("ldmatrix.sync.aligned.m8n8.x4.shared.b16 {%0,%1,%2,%3}, [%4];" \
        : "=r"((R)[0]), "=r"((R)[1]), "=r"((R)[2]), "=r"((R)[3]) : "r"(A))

// ---------------- main kernel ----------------
__global__ __launch_bounds__(NTHREADS)
void lcnn_mma_kernel(const int* __restrict__ NS,
                     const float* __restrict__ bias,
                     float* __restrict__ out)
{
    extern __shared__ char smem[];
    const int tid = threadIdx.x;
    const int wid = tid >> 5;     // 0..7
    const int lid = tid & 31;
    const int g   = lid >> 2;     // 0..7
    const int tg  = lid & 3;      // 0..3
    const int blk = blockIdx.x;

    const int R0    = blk * BM;
    const int valid = min(BM, TOTROWS - R0);

    if (tid < OUTF) *(float*)(smem + SM_BIAS + tid * 4) = bias[tid];

    int* idx_sm = (int*)(smem + SM_IDX);
    for (int i = tid; i < BM * NNEIGH; i += NTHREADS)
        idx_sm[i] = (i < valid * NNEIGH) ? NS[(long)R0 * NNEIGH + i] : 0;
    __syncthreads();     // idx visible before first gather

    const uint4* Xhi4 = (const uint4*)g_Xhi;
    const uint4* Xlo4 = (const uint4*)g_Xlo;
    const uint4* GWh4 = (const uint4*)g_Whi;
    const uint4* GWl4 = (const uint4*)g_Wlo;

    const uint32_t A0 = smem_u32(smem + SM_A);
    const uint32_t W0 = smem_u32(smem + SM_W);

    // ldmatrix lane constants (swizzle xor reduces to per-lane constant)
    const uint32_t xorv  = (uint32_t)((lid & 7) * 16);
    const uint32_t arow  = (uint32_t)((wid * 16 + ((lid >> 3) & 1) * 8 + (lid & 7)) * 128);
    const uint32_t aksel = (uint32_t)(((lid >> 4) & 1) * 16);
    const uint32_t wrowb = (uint32_t)(((lid >> 4) & 1) * 8 + (lid & 7));
    const uint32_t wksel = (uint32_t)(((lid >> 3) & 1) * 16);

    float acc[8][4];
    #pragma unroll
    for (int nt = 0; nt < 8; nt++)
        #pragma unroll
        for (int e = 0; e < 4; e++)
            acc[nt][e] = 0.0f;

    // stage chunk c into buffer b via cp.async (one commit group)
    auto stage = [&](int c, int b) {
        const uint32_t Ah = A0 + b * ABUF, Al = Ah + 16384;
        const uint32_t Wh = W0 + b * WBUF, Wl = Wh + 8192;
        #pragma unroll
        for (int it = 0; it < 4; it++) {
            int linear = tid + it * NTHREADS;     // < 1024
            int m = linear >> 3, u = linear & 7;
            int nb = idx_sm[m * NNEIGH + c];
            uint32_t off = (uint32_t)(m * 128) +
                           ((uint32_t)(u * 16) ^ (uint32_t)((m & 7) * 16));
            cp16(Ah + off, Xhi4 + nb * 8 + u);
            cp16(Al + off, Xlo4 + nb * 8 + u);
        }
        #pragma unroll
        for (int it = 0; it < 2; it++) {
            int v = tid + it * NTHREADS;          // < 512
            int n = v >> 3, uu = v & 7;
            uint32_t off = (uint32_t)(n * 128) +
                           ((uint32_t)(uu * 16) ^ (uint32_t)((n & 7) * 16));
            cp16(Wh + off, GWh4 + c * 512 + v);
            cp16(Wl + off, GWl4 + c * 512 + v);
        }
        CP_COMMIT();
    };

    stage(0, 0);

    for (int c = 0; c < NCHUNK; c++) {
        const int b = c & 1;
        CP_WAIT0();          // chunk c copies (this thread) complete
        __syncthreads();     // all threads' copies visible; all done with MMA c-1
        if (c + 1 < NCHUNK) stage(c + 1, 1 - b);   // overlaps MMA below

        const uint32_t Ahc = A0 + b * ABUF;
        const uint32_t Alc = Ahc + 16384;
        const uint32_t Whc = W0 + b * WBUF;
        const uint32_t Wlc = Whc + 8192;
        #pragma unroll
        for (int ks = 0; ks < 4; ks++) {
            const uint32_t ka = ((uint32_t)(ks * 32) + aksel) ^ xorv;
            const uint32_t kw = ((uint32_t)(ks * 32) + wksel) ^ xorv;
            uint32_t ah[4], al[4];
            LDSM_X4(ah, Ahc + arow + ka);
            LDSM_X4(al, Alc + arow + ka);
            #pragma unroll
            for (int np = 0; np < 4; np++) {
                const uint32_t woff = (uint32_t)((np * 16 + wrowb) * 128) + kw;
                uint32_t bh[4], bl[4];
                LDSM_X4(bh, Whc + woff);
                LDSM_X4(bl, Wlc + woff);
                mma_bf16(acc[np * 2 + 0], ah, bh[0], bh[1]);
                mma_bf16(acc[np * 2 + 1], ah, bh[2], bh[3]);
                mma_bf16(acc[np * 2 + 0], ah, bl[0], bl[1]);
                mma_bf16(acc[np * 2 + 1], ah, bl[2], bl[3]);
                mma_bf16(acc[np * 2 + 0], al, bh[0], bh[1]);
                mma_bf16(acc[np * 2 + 1], al, bh[2], bh[3]);
            }
        }
    }

    // Epilogue: bias + shifted softplus -> smem red buffer [128][64] f32.
    // red aliases A buf 0; final MMA read buf 1, and writes here touch only
    // this warp's rows. __syncthreads below orders the reduction.
    float* red = (float*)(smem + SM_RED);
    const float* bsm = (const float*)(smem + SM_BIAS);
    const int row0 = wid * 16 + g;
    #pragma unroll
    for (int nt = 0; nt < 8; nt++) {
        const int col = nt * 8 + 2 * tg;
        const float b0 = bsm[col], b1 = bsm[col + 1];
        float x, s0, s1;
        x = acc[nt][0] + b0;
        s0 = fmaxf(x, 0.0f) + __logf(1.0f + __expf(-fabsf(x))) - LN2F;
        x = acc[nt][1] + b1;
        s1 = fmaxf(x, 0.0f) + __logf(1.0f + __expf(-fabsf(x))) - LN2F;
        *(float2*)&red[row0 * 64 + col] = make_float2(s0, s1);
        x = acc[nt][2] + b0;
        s0 = fmaxf(x, 0.0f) + __logf(1.0f + __expf(-fabsf(x))) - LN2F;
        x = acc[nt][3] + b1;
        s1 = fmaxf(x, 0.0f) + __logf(1.0f + __expf(-fabsf(x))) - LN2F;
        *(float2*)&red[(row0 + 8) * 64 + col] = make_float2(s0, s1);
    }
    __syncthreads();

    // Per-site perm sums. Sites can straddle tile boundaries -> <=2 atomic
    // contributions per output; float add of 2 terms is order-independent.
    {
        int s0 = R0 / NPERM;
        int s1 = (R0 + valid - 1) / NPERM;
        int nout = (s1 - s0 + 1) * OUTF;
        for (int i = tid; i < nout; i += NTHREADS) {
            int site = s0 + (i >> 6);
            int col  = i & 63;
            int rbeg = max(site * NPERM, R0);
            int rend = min(site * NPERM + NPERM, R0 + valid);
            float v = 0.0f;
            for (int r = rbeg; r < rend; r++)
                v += red[(r - R0) * 64 + col];
            atomicAdd(&out[(long)site * OUTF + col], v);
        }
    }
}

extern "C" void kernel_launch(void* const* d_in, const int* in_sizes, int n_in,
                              void* d_out, int out_size) {
    const float* X  = (const float*)d_in[0];   // X_sites (50000,64) f32
    const int*   NS = (const int*)  d_in[1];   // X_NSs   (50000,12,8) i32
    const float* W  = (const float*)d_in[2];   // W       (64,512) f32
    const float* b  = (const float*)d_in[3];   // b       (64,) f32
    float* out = (float*)d_out;                // (50000,64) f32

    cudaFuncSetAttribute(lcnn_mma_kernel,
                         cudaFuncAttributeMaxDynamicSharedMemorySize, SM_TOTAL);

    split_W_kernel<<<(OUTF * INF + 255) / 256, 256>>>(W);
    split_X_kernel<<<(NSITES * 64 + 255) / 256, 256>>>(X);
    zero_out_kernel<<<(NSITES * OUTF + 255) / 256, 256>>>(out);
    lcnn_mma_kernel<<<NBLOCKS, NTHREADS, SM_TOTAL>>>(NS, b, out);
}

// round 14
// speedup vs baseline: 1.5650x; 1.0271x over previous
#include <cuda_runtime.h>
#include <cuda_bf16.h>
#include <cstdint>

#define NSITES   50000
#define NPERM    12
#define NNEIGH   8
#define INF      512
#define OUTF     64
#define LN2F     0.6931471805599453f

#define TOTROWS  (NSITES * NPERM)                  // 600000
#define BM       128
#define NBLOCKS  ((TOTROWS + BM - 1) / BM)         // 4688
#define NTHREADS 256
#define NCHUNK   8

// ---------------- SMEM layout (bytes, dynamic) ----------------
#define SM_BIAS  0                      // 64 f32 = 256 B
#define SM_IDX   256                    // 128*8 int = 4096 B
#define SM_W     5120                   // 2 bufs x (hi 8192 + lo 8192)
#define WBUF     16384
#define SM_A     38912                  // 2 bufs x (hi 16384 + lo 16384)
#define ABUF     32768
#define SM_TOTAL 104448
#define SM_RED   SM_A                   // epilogue reuse: 128*64 f32 = 32768 B

// ---------------- global split buffers ----------------
__device__ __nv_bfloat16 g_Whi[NCHUNK * 64 * 64];   // [c][n][kk], kk contiguous
__device__ __nv_bfloat16 g_Wlo[NCHUNK * 64 * 64];
__device__ __nv_bfloat16 g_Xhi[NSITES * 64];
__device__ __nv_bfloat16 g_Xlo[NSITES * 64];

// ---------------- pre-kernels ----------------
__global__ void split_W_kernel(const float* __restrict__ W) {
    int i = blockIdx.x * blockDim.x + threadIdx.x;
    if (i < OUTF * INF) {
        int n = i >> 9, k = i & 511, c = k >> 6, kk = k & 63;
        float v = W[i];
        __nv_bfloat16 h = __float2bfloat16(v);
        float r = v - __bfloat162float(h);
        int j = c * 4096 + n * 64 + kk;
        g_Whi[j] = h;
        g_Wlo[j] = __float2bfloat16(r);
    }
}
__global__ void split_X_kernel(const float* __restrict__ X) {
    int i = blockIdx.x * blockDim.x + threadIdx.x;
    if (i < NSITES * 64) {
        float v = X[i];
        __nv_bfloat16 h = __float2bfloat16(v);
        g_Xhi[i] = h;
        g_Xlo[i] = __float2bfloat16(v - __bfloat162float(h));
    }
}
__global__ void zero_out_kernel(float* __restrict__ out) {
    int i = blockIdx.x * blockDim.x + threadIdx.x;
    if (i < NSITES * OUTF) out[i] = 0.0f;
}

// ---------------- PTX helpers ----------------
__device__ __forceinline__ uint32_t smem_u32(const void* p) {
    uint32_t a;
    asm("{ .reg .u64 t; cvta.to.shared.u64 t, %1; cvt.u32.u64 %0, t; }" : "=r"(a) : "l"(p));
    return a;
}
__device__ __forceinline__ void cp16(uint32_t dst, const void* src) {
    asm volatile("cp.async.cg.shared.global [%0], [%1], 16;" :: "r"(dst), "l"(src) : "memory");
}
#define CP_COMMIT() asm volatile("cp.async.commit_group;" ::: "memory")
#define CP_WAIT0()  asm volatile("cp.async.wait_group 0;" ::: "memory")
__device__ __forceinline__ void mma_bf16(float* d, const uint32_t* a,
                                         uint32_t b0, uint32_t b1) {
    asm volatile(
        "mma.sync.aligned.m16n8k16.row.col.f32.bf16.bf16.f32 "
        "{%0,%1,%2,%3}, {%4,%5,%6,%7}, {%8,%9}, {%0,%1,%2,%3};\n"
        : "+f"(d[0]), "+f"(d[1]), "+f"(d[2]), "+f"(d[3])
        : "r"(a[0]), "r"(a[1]), "r"(a[2]), "r"(a[3]), "r"(b0), "r"(b1));
}
#define LDSM_X4(R, A) \
    asm volatile("ldmatrix.sync.aligned.m8n8.x4.shared.b16 {%0,%1,%2,%3}, [%4];" \
        : "=r"((R)[0]), "=r"((R)[1]), "=r"((R)[2]), "=r"((R)[3]) : "r"(A))

// ---------------- main kernel ----------------
__global__ __launch_bounds__(NTHREADS)
void lcnn_mma_kernel(const int* __restrict__ NS,
                     const float* __restrict__ bias,
                     float* __restrict__ out)
{
    extern __shared__ char smem[];
    const int tid = threadIdx.x;
    const int wid = tid >> 5;     // 0..7
    const int lid = tid & 31;
    const int g   = lid >> 2;     // 0..7
    const int tg  = lid & 3;      // 0..3
    const int wm  = wid >> 1;     // 0..3 : warp row block (32 rows)
    const int wn  = wid & 1;      // 0..1 : warp col block (32 cols)
    const int blk = blockIdx.x;

    const int R0    = blk * BM;
    const int valid = min(BM, TOTROWS - R0);

    if (tid < OUTF) *(float*)(smem + SM_BIAS + tid * 4) = bias[tid];

    int* idx_sm = (int*)(smem + SM_IDX);
    for (int i = tid; i < BM * NNEIGH; i += NTHREADS)
        idx_sm[i] = (i < valid * NNEIGH) ? NS[(long)R0 * NNEIGH + i] : 0;
    __syncthreads();     // idx visible before first gather

    const uint4* Xhi4 = (const uint4*)g_Xhi;
    const uint4* Xlo4 = (const uint4*)g_Xlo;
    const uint4* GWh4 = (const uint4*)g_Whi;
    const uint4* GWl4 = (const uint4*)g_Wlo;

    const uint32_t A0 = smem_u32(smem + SM_A);
    const uint32_t W0 = smem_u32(smem + SM_W);

    // ---- hoisted ldmatrix lane constants (swizzle xor is per-lane constant) ----
    const uint32_t xorv  = (uint32_t)((lid & 7) * 16);
    const uint32_t aksel = (uint32_t)(((lid >> 4) & 1) * 16);
    const uint32_t wksel = (uint32_t)(((lid >> 3) & 1) * 16);
    const uint32_t arow0 = (uint32_t)((wm * 32 + ((lid >> 3) & 1) * 8 + (lid & 7)) * 128);
    const uint32_t arow1 = arow0 + 16 * 128;
    const uint32_t wrow0 = (uint32_t)((wn * 32 + ((lid >> 4) & 1) * 8 + (lid & 7)) * 128);
    const uint32_t wrow1 = wrow0 + 16 * 128;

    float acc[2][4][4];
    #pragma unroll
    for (int mt = 0; mt < 2; mt++)
        #pragma unroll
        for (int nt = 0; nt < 4; nt++)
            #pragma unroll
            for (int e = 0; e < 4; e++)
                acc[mt][nt][e] = 0.0f;

    // stage chunk c into buffer b via cp.async (one commit group)
    auto stage = [&](int c, int b) {
        const uint32_t Ah = A0 + b * ABUF, Al = Ah + 16384;
        const uint32_t Wh = W0 + b * WBUF, Wl = Wh + 8192;
        #pragma unroll
        for (int it = 0; it < 4; it++) {
            int linear = tid + it * NTHREADS;     // < 1024
            int m = linear >> 3, u = linear & 7;
            int nb = idx_sm[m * NNEIGH + c];
            uint32_t off = (uint32_t)(m * 128) +
                           ((uint32_t)(u * 16) ^ (uint32_t)((m & 7) * 16));
            cp16(Ah + off, Xhi4 + nb * 8 + u);
            cp16(Al + off, Xlo4 + nb * 8 + u);
        }
        #pragma unroll
        for (int it = 0; it < 2; it++) {
            int v = tid + it * NTHREADS;          // < 512
            int n = v >> 3, uu = v & 7;
            uint32_t off = (uint32_t)(n * 128) +
                           ((uint32_t)(uu * 16) ^ (uint32_t)((n & 7) * 16));
            cp16(Wh + off, GWh4 + c * 512 + v);
            cp16(Wl + off, GWl4 + c * 512 + v);
        }
        CP_COMMIT();
    };

    stage(0, 0);

    for (int c = 0; c < NCHUNK; c++) {
        const int b = c & 1;
        CP_WAIT0();          // chunk c copies (this thread) complete
        __syncthreads();     // all threads' copies visible; all done with MMA c-1
        if (c + 1 < NCHUNK) stage(c + 1, 1 - b);   // overlaps MMA below

        const uint32_t Ahc = A0 + b * ABUF;
        const uint32_t Alc = Ahc + 16384;
        const uint32_t Whc = W0 + b * WBUF;
        const uint32_t Wlc = Whc + 8192;
        #pragma unroll
        for (int ks = 0; ks < 4; ks++) {
            const uint32_t ka = ((uint32_t)(ks * 32) + aksel) ^ xorv;
            const uint32_t kw = ((uint32_t)(ks * 32) + wksel) ^ xorv;
            uint32_t ah[2][4], al[2][4], bh[2][4], bl[2][4];
            LDSM_X4(ah[0], Ahc + arow0 + ka);
            LDSM_X4(ah[1], Ahc + arow1 + ka);
            LDSM_X4(al[0], Alc + arow0 + ka);
            LDSM_X4(al[1], Alc + arow1 + ka);
            LDSM_X4(bh[0], Whc + wrow0 + kw);
            LDSM_X4(bh[1], Whc + wrow1 + kw);
            LDSM_X4(bl[0], Wlc + wrow0 + kw);
            LDSM_X4(bl[1], Wlc + wrow1 + kw);
            #pragma unroll
            for (int mt = 0; mt < 2; mt++) {
                #pragma unroll
                for (int np = 0; np < 2; np++) {
                    mma_bf16(acc[mt][np * 2 + 0], ah[mt], bh[np][0], bh[np][1]);
                    mma_bf16(acc[mt][np * 2 + 1], ah[mt], bh[np][2], bh[np][3]);
                    mma_bf16(acc[mt][np * 2 + 0], ah[mt], bl[np][0], bl[np][1]);
                    mma_bf16(acc[mt][np * 2 + 1], ah[mt], bl[np][2], bl[np][3]);
                    mma_bf16(acc[mt][np * 2 + 0], al[mt], bh[np][0], bh[np][1]);
                    mma_bf16(acc[mt][np * 2 + 1], al[mt], bh[np][2], bh[np][3]);
                }
            }
        }
    }

    // Epilogue: bias + shifted softplus -> smem red buffer [128][64] f32.
    float* red = (float*)(smem + SM_RED);
    const float* bsm = (const float*)(smem + SM_BIAS);
    #pragma unroll
    for (int mt = 0; mt < 2; mt++) {
        const int row0 = wm * 32 + mt * 16 + g;
        #pragma unroll
        for (int nt = 0; nt < 4; nt++) {
            const int col = wn * 32 + nt * 8 + 2 * tg;
            const float b0 = bsm[col], b1 = bsm[col + 1];
            float x, s0, s1;
            x = acc[mt][nt][0] + b0;
            s0 = fmaxf(x, 0.0f) + __logf(1.0f + __expf(-fabsf(x))) - LN2F;
            x = acc[mt][nt][1] + b1;
            s1 = fmaxf(x, 0.0f) + __logf(1.0f + __expf(-fabsf(x))) - LN2F;
            *(float2*)&red[row0 * 64 + col] = make_float2(s0, s1);
            x = acc[mt][nt][2] + b0;
            s0 = fmaxf(x, 0.0f) + __logf(1.0f + __expf(-fabsf(x))) - LN2F;
            x = acc[mt][nt][3] + b1;
            s1 = fmaxf(x, 0.0f) + __logf(1.0f + __expf(-fabsf(x))) - LN2F;
            *(float2*)&red[(row0 + 8) * 64 + col] = make_float2(s0, s1);
        }
    }
    __syncthreads();

    // Per-site perm sums. Sites can straddle tile boundaries -> <=2 atomic
    // contributions per output; float add of 2 terms is order-independent.
    {
        int s0 = R0 / NPERM;
        int s1 = (R0 + valid - 1) / NPERM;
        int nout = (s1 - s0 + 1) * OUTF;
        for (int i = tid; i < nout; i += NTHREADS) {
            int site = s0 + (i >> 6);
            int col  = i & 63;
            int rbeg = max(site * NPERM, R0);
            int rend = min(site * NPERM + NPERM, R0 + valid);
            float v = 0.0f;
            for (int r = rbeg; r < rend; r++)
                v += red[(r - R0) * 64 + col];
            atomicAdd(&out[(long)site * OUTF + col], v);
        }
    }
}

extern "C" void kernel_launch(void* const* d_in, const int* in_sizes, int n_in,
                              void* d_out, int out_size) {
    const float* X  = (const float*)d_in[0];   // X_sites (50000,64) f32
    const int*   NS = (const int*)  d_in[1];   // X_NSs   (50000,12,8) i32
    const float* W  = (const float*)d_in[2];   // W       (64,512) f32
    const float* b  = (const float*)d_in[3];   // b       (64,) f32
    float* out = (float*)d_out;                // (50000,64) f32

    cudaFuncSetAttribute(lcnn_mma_kernel,
                         cudaFuncAttributeMaxDynamicSharedMemorySize, SM_TOTAL);

    split_W_kernel<<<(OUTF * INF + 255) / 256, 256>>>(W);
    split_X_kernel<<<(NSITES * 64 + 255) / 256, 256>>>(X);
    zero_out_kernel<<<(NSITES * OUTF + 255) / 256, 256>>>(out);
    lcnn_mma_kernel<<<NBLOCKS, NTHREADS, SM_TOTAL>>>(NS, b, out);
}